// round 1
// baseline (speedup 1.0000x reference)
#include <cuda_runtime.h>
#include <math.h>

// ---------------- problem constants ----------------
#define NPIX 131072
#define DIMV 720
#define NCLS 19
#define NPRO 10
#define KM   190        // NCLS*NPRO
#define KMP  192        // padded
#define SKEPS_INV 20.0f // 1/0.05

// output layout (concatenated, fp32): out_seg[N,19] | contrast[N,190] | proto_target[N] | protos_new[190,720]
#define OFF_SEG 0
#define OFF_CON ((size_t)NPIX * 19)
#define OFF_PT  (OFF_CON + (size_t)NPIX * 190)
#define OFF_PN  (OFF_PT + (size_t)NPIX)

// ---------------- device scratch ----------------
__device__ float g_c[(size_t)NPIX * DIMV];     // normalized pixel embeddings (377 MB)
__device__ float g_Pt[DIMV * KMP];             // normalized protos, transposed+padded [d][j]
__device__ float g_Pn[KM * DIMV];              // normalized protos row-major [j][d]
__device__ float g_E[(size_t)NPIX * NPRO];     // exp(sim_gt/eps) per pixel
__device__ float g_S[KM];                      // Sinkhorn column sums
__device__ float g_b[KM];                      // Sinkhorn column scalings
__device__ float g_Bk[NCLS];                   // pixels per class
__device__ float g_nkm[KM];                    // hard-assignment counts (correct pixels)
__device__ float g_f[KM * DIMV];               // prototype feature accumulators
__device__ unsigned char g_corr[NPIX];
__device__ unsigned char g_idx[NPIX];

// ---------------- helpers ----------------
__device__ __forceinline__ float warp_sum(float v) {
    #pragma unroll
    for (int o = 16; o; o >>= 1) v += __shfl_xor_sync(0xffffffffu, v, o);
    return v;
}

__device__ __forceinline__ float block_sum_256(float v) {
    __shared__ float sh[8];
    int lane = threadIdx.x & 31, w = threadIdx.x >> 5;
    v = warp_sum(v);
    if (lane == 0) sh[w] = v;
    __syncthreads();
    float r = 0.f;
    if (threadIdx.x < 8) r = sh[threadIdx.x];
    if (w == 0) {
        #pragma unroll
        for (int o = 4; o; o >>= 1) r += __shfl_xor_sync(0xffffffffu, r, o);
    }
    if (threadIdx.x == 0) sh[0] = r;
    __syncthreads();
    r = sh[0];
    __syncthreads();   // protect sh for subsequent calls
    return r;
}

// ---------------- 0: zero accumulators ----------------
__global__ void zero_kernel() {
    int i = blockIdx.x * blockDim.x + threadIdx.x;
    int stride = gridDim.x * blockDim.x;
    for (int j = i; j < KM * DIMV; j += stride) g_f[j] = 0.f;
    for (int j = i; j < DIMV * KMP; j += stride) g_Pt[j] = 0.f;
    for (int j = i; j < KM; j += stride) { g_S[j] = 0.f; g_nkm[j] = 0.f; }
    for (int j = i; j < NCLS; j += stride) g_Bk[j] = 0.f;
}

// ---------------- 1: l2-normalize prototypes ----------------
__global__ void norm_protos(const float* __restrict__ proto) {
    int row = blockIdx.x;                   // 0..189
    const float* p = proto + (size_t)row * DIMV;
    float sq = 0.f;
    for (int d = threadIdx.x; d < DIMV; d += blockDim.x) { float v = p[d]; sq += v * v; }
    sq = block_sum_256(sq);
    float inv = 1.f / fmaxf(sqrtf(sq), 1e-12f);
    for (int d = threadIdx.x; d < DIMV; d += blockDim.x) {
        float v = p[d] * inv;
        g_Pn[(size_t)row * DIMV + d] = v;
        g_Pt[(size_t)d * KMP + row] = v;
    }
}

// ---------------- 2: per-pixel LN + L2 -> g_c ----------------
__global__ void prep_pixels(const float* __restrict__ x,
                            const float* __restrict__ fg,
                            const float* __restrict__ fb) {
    int warp = (blockIdx.x * blockDim.x + threadIdx.x) >> 5;
    int lane = threadIdx.x & 31;
    if (warp >= NPIX) return;
    const float* row = x + (size_t)warp * DIMV;

    float v[23];
    float s = 0.f;
    #pragma unroll
    for (int i = 0; i < 23; ++i) {
        int d = lane + 32 * i;
        float t = (d < DIMV) ? row[d] : 0.f;
        v[i] = t; s += t;
    }
    s = warp_sum(s);
    float mu = s / (float)DIMV;
    float sq = 0.f;
    #pragma unroll
    for (int i = 0; i < 23; ++i) {
        int d = lane + 32 * i;
        if (d < DIMV) { float t = v[i] - mu; sq += t * t; }
    }
    sq = warp_sum(sq);
    float r = rsqrtf(sq / (float)DIMV + 1e-5f);
    float ny = 0.f;
    #pragma unroll
    for (int i = 0; i < 23; ++i) {
        int d = lane + 32 * i;
        if (d < DIMV) {
            float y = (v[i] - mu) * r * fg[d] + fb[d];
            v[i] = y; ny += y * y;
        }
    }
    ny = warp_sum(ny);
    float inv = 1.f / fmaxf(sqrtf(ny), 1e-12f);
    float* out = g_c + (size_t)warp * DIMV;
    #pragma unroll
    for (int i = 0; i < 23; ++i) {
        int d = lane + 32 * i;
        if (d < DIMV) out[d] = v[i] * inv;
    }
}

// ---------------- 3: GEMM (sim = c @ P^T) with fused epilogue ----------------
#define BM 32
#define BN 192
#define BK 16

__global__ void __launch_bounds__(256) gemm_epi(const float* __restrict__ mg,
                                                const float* __restrict__ mb,
                                                const float* __restrict__ pg,
                                                const float* __restrict__ pb,
                                                const int*   __restrict__ gt,
                                                float* __restrict__ out) {
    __shared__ float As[BK][BM];
    __shared__ float Bs[BK][BN];
    __shared__ float sim_s[BM][BN];

    int t  = threadIdx.x;
    int tc = t & 15;          // 0..15 -> 12 N-cols each
    int tr = t >> 4;          // 0..15 -> 2 M-rows each
    int bm0 = blockIdx.x * BM;

    float acc0[12], acc1[12];
    #pragma unroll
    for (int j = 0; j < 12; ++j) { acc0[j] = 0.f; acc1[j] = 0.f; }

    int arow = t >> 3;            // 0..31
    int acol = (t & 7) * 2;       // 0..14
    const float* Ag = g_c + (size_t)(bm0 + arow) * DIMV + acol;

    for (int k0 = 0; k0 < DIMV; k0 += BK) {
        float2 av = *(const float2*)(Ag + k0);
        As[acol][arow]     = av.x;
        As[acol + 1][arow] = av.y;
        #pragma unroll
        for (int i = 0; i < 3; ++i) {
            int idx = t + i * 256;            // 0..767 float4s
            int br = idx / 48;
            int bc = (idx % 48) * 4;
            *(float4*)&Bs[br][bc] = *(const float4*)(g_Pt + (size_t)(k0 + br) * KMP + bc);
        }
        __syncthreads();
        #pragma unroll
        for (int kk = 0; kk < BK; ++kk) {
            float2 a = *(const float2*)&As[kk][tr * 2];
            float4 b0 = *(const float4*)&Bs[kk][tc * 12];
            float4 b1 = *(const float4*)&Bs[kk][tc * 12 + 4];
            float4 b2 = *(const float4*)&Bs[kk][tc * 12 + 8];
            float bv[12] = {b0.x, b0.y, b0.z, b0.w, b1.x, b1.y, b1.z, b1.w,
                            b2.x, b2.y, b2.z, b2.w};
            #pragma unroll
            for (int j = 0; j < 12; ++j) {
                acc0[j] = fmaf(a.x, bv[j], acc0[j]);
                acc1[j] = fmaf(a.y, bv[j], acc1[j]);
            }
        }
        __syncthreads();
    }

    // stage tile
    #pragma unroll
    for (int j = 0; j < 12; ++j) {
        sim_s[tr * 2][tc * 12 + j]     = acc0[j];
        sim_s[tr * 2 + 1][tc * 12 + j] = acc1[j];
    }
    __syncthreads();

    // epilogue: 8 warps x 4 rows
    int w = t >> 5, lane = t & 31;
    for (int q = 0; q < 4; ++q) {
        int r = w * 4 + q;
        int n = bm0 + r;
        int gtn = gt[n];

        // LN over 190 (contrast logits)
        float s = 0.f, sq = 0.f;
        #pragma unroll
        for (int it = 0; it < 6; ++it) {
            int j = lane + it * 32;
            if (j < KM) { float v = sim_s[r][j]; s += v; sq += v * v; }
        }
        s = warp_sum(s); sq = warp_sum(sq);
        float mu = s / (float)KM;
        float var = fmaxf(sq / (float)KM - mu * mu, 0.f);
        float rv = rsqrtf(var + 1e-5f);
        #pragma unroll
        for (int it = 0; it < 6; ++it) {
            int j = lane + it * 32;
            if (j < KM)
                out[OFF_CON + (size_t)n * KM + j] = (sim_s[r][j] - mu) * rv * pg[j] + pb[j];
        }

        // class max + LN over 19 (out_seg)
        float mx = -1e30f;
        if (lane < NCLS) {
            #pragma unroll
            for (int m = 0; m < NPRO; ++m) mx = fmaxf(mx, sim_s[r][lane * NPRO + m]);
        }
        float cm  = (lane < NCLS) ? mx : 0.f;
        float cm2 = (lane < NCLS) ? mx * mx : 0.f;
        float s19 = warp_sum(cm), sq19 = warp_sum(cm2);
        float mu19 = s19 / (float)NCLS;
        float var19 = fmaxf(sq19 / (float)NCLS - mu19 * mu19, 0.f);
        float rv19 = rsqrtf(var19 + 1e-5f);
        float o = 0.f;
        if (lane < NCLS) {
            o = (mx - mu19) * rv19 * mg[lane] + mb[lane];
            out[OFF_SEG + (size_t)n * NCLS + lane] = o;
        }
        // argmax (first occurrence on ties)
        float bv = (lane < NCLS) ? o : -INFINITY;
        int bi = lane;
        #pragma unroll
        for (int off = 16; off; off >>= 1) {
            float ov = __shfl_xor_sync(0xffffffffu, bv, off);
            int   oi = __shfl_xor_sync(0xffffffffu, bi, off);
            if (ov > bv || (ov == bv && oi < bi)) { bv = ov; bi = oi; }
        }
        if (lane == 0) {
            g_corr[n] = (bi == gtn) ? 1 : 0;
            atomicAdd(&g_Bk[gtn], 1.f);
        }
        if (lane < NPRO)
            g_E[(size_t)n * NPRO + lane] = expf(sim_s[r][gtn * NPRO + lane] * SKEPS_INV);
    }
}

// ---------------- 4: Sinkhorn column-sum accumulation ----------------
__global__ void sk_accum(const int* __restrict__ gt, int pass) {
    __shared__ float Sl[KM];
    int t = threadIdx.x;
    if (t < KM) Sl[t] = 0.f;
    __syncthreads();
    int n = blockIdx.x * blockDim.x + t;
    if (n < NPIX) {
        int k = gt[n];
        const float* E = g_E + (size_t)n * NPRO;
        float e[NPRO];
        #pragma unroll
        for (int m = 0; m < NPRO; ++m) e[m] = E[m];
        float a = 1.f;
        if (pass) {
            const float* bb = g_b + k * NPRO;
            float d = 0.f;
            #pragma unroll
            for (int m = 0; m < NPRO; ++m) d += e[m] * bb[m];
            a = 1.f / (g_Bk[k] * d);
        }
        #pragma unroll
        for (int m = 0; m < NPRO; ++m) atomicAdd(&Sl[k * NPRO + m], e[m] * a);
    }
    __syncthreads();
    if (t < KM) atomicAdd(&g_S[t], Sl[t]);
}

__global__ void sk_fin() {
    int t = threadIdx.x;
    if (t < KM) {
        float s = g_S[t];
        g_b[t] = (s > 0.f) ? 1.f / (10.f * s) : 0.f;
        g_S[t] = 0.f;
    }
}

// ---------------- 5: hard assignment + proto_target ----------------
__global__ void sk_final(const int* __restrict__ gt, float* __restrict__ out) {
    int n = blockIdx.x * blockDim.x + threadIdx.x;
    if (n >= NPIX) return;
    int k = gt[n];
    const float* E = g_E + (size_t)n * NPRO;
    const float* bb = g_b + k * NPRO;
    float best = -1.f; int bi = 0;
    #pragma unroll
    for (int m = 0; m < NPRO; ++m) {
        float wv = E[m] * bb[m];
        if (wv > best) { best = wv; bi = m; }
    }
    out[OFF_PT + n] = (float)(bi + NPRO * k);
    g_idx[n] = (unsigned char)bi;
    if (g_corr[n]) atomicAdd(&g_nkm[k * NPRO + bi], 1.f);
}

// ---------------- 6: accumulate f over correct pixels ----------------
__global__ void f_accum(const int* __restrict__ gt) {
    int warp = (blockIdx.x * blockDim.x + threadIdx.x) >> 5;
    int lane = threadIdx.x & 31;
    if (warp >= NPIX) return;
    if (!g_corr[warp]) return;
    int k = gt[warp], m = g_idx[warp];
    float* f = g_f + (size_t)(k * NPRO + m) * DIMV;
    const float* c = g_c + (size_t)warp * DIMV;
    for (int d = lane; d < DIMV; d += 32) atomicAdd(&f[d], c[d]);
}

// ---------------- 7: prototype EMA update ----------------
__global__ void update_protos(float* __restrict__ out) {
    int row = blockIdx.x;                 // 0..189
    int k = row / NPRO;
    const float* f = g_f + (size_t)row * DIMV;
    const float* p = g_Pn + (size_t)row * DIMV;

    float sq = 0.f;
    for (int d = threadIdx.x; d < DIMV; d += blockDim.x) { float v = f[d]; sq += v * v; }
    sq = block_sum_256(sq);
    float invf = 1.f / fmaxf(sqrtf(sq), 1e-12f);

    float nk = g_nkm[row];
    float ksum = 0.f;
    #pragma unroll
    for (int m = 0; m < NPRO; ++m) ksum += g_nkm[k * NPRO + m];
    bool valid = (nk != 0.f) && (ksum > 0.f);

    float squ = 0.f;
    for (int d = threadIdx.x; d < DIMV; d += blockDim.x) {
        float pv = p[d];
        float u = valid ? (0.999f * pv + 0.001f * f[d] * invf) : pv;
        squ += u * u;
    }
    squ = block_sum_256(squ);
    float invu = 1.f / fmaxf(sqrtf(squ), 1e-12f);
    for (int d = threadIdx.x; d < DIMV; d += blockDim.x) {
        float pv = p[d];
        float u = valid ? (0.999f * pv + 0.001f * f[d] * invf) : pv;
        out[OFF_PN + (size_t)row * DIMV + d] = u * invu;
    }
}

// ---------------- launch ----------------
extern "C" void kernel_launch(void* const* d_in, const int* in_sizes, int n_in,
                              void* d_out, int out_size) {
    const float* x     = (const float*)d_in[0];
    const float* proto = (const float*)d_in[1];
    const float* fn_g  = (const float*)d_in[2];
    const float* fn_b  = (const float*)d_in[3];
    const float* mn_g  = (const float*)d_in[4];
    const float* mn_b  = (const float*)d_in[5];
    const float* pn_g  = (const float*)d_in[6];
    const float* pn_b  = (const float*)d_in[7];
    const int*   gt    = (const int*)d_in[8];
    float* out = (float*)d_out;

    zero_kernel<<<540, 256>>>();
    norm_protos<<<KM, 256>>>(proto);
    prep_pixels<<<NPIX / 8, 256>>>(x, fn_g, fn_b);
    gemm_epi<<<NPIX / BM, 256>>>(mn_g, mn_b, pn_g, pn_b, gt, out);
    // Sinkhorn: 3 iterations of column scaling (argmax depends only on E*b)
    sk_accum<<<NPIX / 256, 256>>>(gt, 0);
    sk_fin<<<1, 192>>>();
    sk_accum<<<NPIX / 256, 256>>>(gt, 1);
    sk_fin<<<1, 192>>>();
    sk_accum<<<NPIX / 256, 256>>>(gt, 1);
    sk_fin<<<1, 192>>>();
    sk_final<<<NPIX / 256, 256>>>(gt, out);
    f_accum<<<NPIX / 8, 256>>>(gt);
    update_protos<<<KM, 256>>>(out);
}

// round 3
// speedup vs baseline: 2.3440x; 2.3440x over previous
#include <cuda_runtime.h>
#include <cuda_bf16.h>
#include <math.h>
#include <stdint.h>

// ---------------- problem constants ----------------
#define NPIX 131072
#define DIMV 720
#define KP   768          // K padded (24 chunks of 32)
#define NCLS 19
#define NPRO 10
#define KM   190
#define SKEPS_INV 20.0f

// output layout (fp32): out_seg[N,19] | contrast[N,190] | proto_target[N] | protos_new[190,720]
#define OFF_SEG 0
#define OFF_CON ((size_t)NPIX * 19)
#define OFF_PT  (OFF_CON + (size_t)NPIX * 190)
#define OFF_PN  (OFF_PT + (size_t)NPIX)

// ---------------- device scratch ----------------
__device__ uint4 g_chi4[(size_t)NPIX * 96];   // pixel embeddings hi bf16 [N][768]
__device__ uint4 g_clo4[(size_t)NPIX * 96];   // pixel embeddings lo bf16
__device__ uint4 g_Phi4[192 * 96];            // protos hi bf16 [192][768] (rows 190,191 zero)
__device__ uint4 g_Plo4[192 * 96];            // protos lo bf16
__device__ float g_Pn[KM * DIMV];             // normalized protos fp32
__device__ float g_E[(size_t)NPIX * NPRO];    // exp(sim_gt/eps)
__device__ float g_S[KM];
__device__ float g_b[KM];
__device__ float g_Bk[NCLS];
__device__ float g_nkm[KM];
__device__ float g_f[KM * DIMV];
__device__ unsigned char g_corr[NPIX];
__device__ unsigned char g_idx[NPIX];

// ---------------- generic helpers ----------------
__device__ __forceinline__ float warp_sum(float v) {
    #pragma unroll
    for (int o = 16; o; o >>= 1) v += __shfl_xor_sync(0xffffffffu, v, o);
    return v;
}

__device__ __forceinline__ float block_sum_256(float v) {
    __shared__ float sh[8];
    int lane = threadIdx.x & 31, w = threadIdx.x >> 5;
    v = warp_sum(v);
    if (lane == 0) sh[w] = v;
    __syncthreads();
    float r = 0.f;
    if (threadIdx.x < 8) r = sh[threadIdx.x];
    if (w == 0) {
        #pragma unroll
        for (int o = 4; o; o >>= 1) r += __shfl_xor_sync(0xffffffffu, r, o);
    }
    if (threadIdx.x == 0) sh[0] = r;
    __syncthreads();
    r = sh[0];
    __syncthreads();
    return r;
}

__device__ __forceinline__ uint32_t smem_u32(const void* p) {
    uint32_t a;
    asm("{ .reg .u64 t; cvta.to.shared.u64 t, %1; cvt.u32.u64 %0, t; }" : "=r"(a) : "l"(p));
    return a;
}

// ---------------- PTX macros: HMMA path (family-common, works on compute_103) ----------------
#define LDSM4(r, addr) \
    asm volatile("ldmatrix.sync.aligned.m8n8.x4.shared.b16 {%0,%1,%2,%3}, [%4];" \
        : "=r"((r)[0]), "=r"((r)[1]), "=r"((r)[2]), "=r"((r)[3]) : "r"(addr))

#define MMA_BF16(c, a, b0, b1) \
    asm volatile("mma.sync.aligned.m16n8k16.row.col.f32.bf16.bf16.f32 " \
        "{%0,%1,%2,%3}, {%4,%5,%6,%7}, {%8,%9}, {%0,%1,%2,%3};" \
        : "+f"((c)[0]), "+f"((c)[1]), "+f"((c)[2]), "+f"((c)[3]) \
        : "r"((a)[0]), "r"((a)[1]), "r"((a)[2]), "r"((a)[3]), "r"(b0), "r"(b1))

#define CP16(dst, src) \
    asm volatile("cp.async.cg.shared.global [%0], [%1], 16;" :: "r"(dst), "l"(src) : "memory")

// ---------------- 0: zero accumulators ----------------
__global__ void zero_kernel() {
    int i = blockIdx.x * blockDim.x + threadIdx.x;
    int stride = gridDim.x * blockDim.x;
    for (int j = i; j < KM * DIMV; j += stride) g_f[j] = 0.f;
    for (int j = i; j < KM; j += stride) { g_S[j] = 0.f; g_nkm[j] = 0.f; }
    for (int j = i; j < NCLS; j += stride) g_Bk[j] = 0.f;
}

// ---------------- 1: l2-normalize prototypes -> bf16 hi/lo + fp32 ----------------
__global__ void norm_protos(const float* __restrict__ proto) {
    int row = blockIdx.x;                   // 0..191 (190,191 zero pad)
    __nv_bfloat16* hi = (__nv_bfloat16*)g_Phi4 + (size_t)row * KP;
    __nv_bfloat16* lo = (__nv_bfloat16*)g_Plo4 + (size_t)row * KP;
    float inv = 0.f;
    const float* p = proto + (size_t)row * DIMV;
    if (row < KM) {
        float sq = 0.f;
        for (int d = threadIdx.x; d < DIMV; d += blockDim.x) { float v = p[d]; sq += v * v; }
        sq = block_sum_256(sq);
        inv = 1.f / fmaxf(sqrtf(sq), 1e-12f);
    } else {
        block_sum_256(0.f);
    }
    for (int d = threadIdx.x; d < KP; d += blockDim.x) {
        float v = (row < KM && d < DIMV) ? p[d] * inv : 0.f;
        __nv_bfloat16 h = __float2bfloat16(v);
        hi[d] = h;
        lo[d] = __float2bfloat16(v - __bfloat162float(h));
        if (row < KM && d < DIMV) g_Pn[(size_t)row * DIMV + d] = v;
    }
}

// ---------------- 2: per-pixel LN + L2 -> bf16 hi/lo (coalesced via SMEM staging) ----------------
__global__ void prep_pixels(const float* __restrict__ x,
                            const float* __restrict__ fg,
                            const float* __restrict__ fb) {
    __shared__ uint4 sh4[8][2][96];          // [warp][hi/lo][96 uint4]
    int w = threadIdx.x >> 5, lane = threadIdx.x & 31;
    int row = blockIdx.x * 8 + w;
    const float* xr = x + (size_t)row * DIMV;
    __nv_bfloat16* shh = (__nv_bfloat16*)sh4[w][0];
    __nv_bfloat16* shl = (__nv_bfloat16*)sh4[w][1];

    float v[23];
    float s = 0.f;
    #pragma unroll
    for (int i = 0; i < 23; ++i) {
        int d = lane + 32 * i;
        float t = (d < DIMV) ? xr[d] : 0.f;
        v[i] = t; s += t;
    }
    s = warp_sum(s);
    float mu = s / (float)DIMV;
    float sq = 0.f;
    #pragma unroll
    for (int i = 0; i < 23; ++i) {
        int d = lane + 32 * i;
        if (d < DIMV) { float t = v[i] - mu; sq += t * t; }
    }
    sq = warp_sum(sq);
    float r = rsqrtf(sq / (float)DIMV + 1e-5f);
    float ny = 0.f;
    #pragma unroll
    for (int i = 0; i < 23; ++i) {
        int d = lane + 32 * i;
        if (d < DIMV) {
            float y = (v[i] - mu) * r * fg[d] + fb[d];
            v[i] = y; ny += y * y;
        }
    }
    ny = warp_sum(ny);
    float inv = 1.f / fmaxf(sqrtf(ny), 1e-12f);
    #pragma unroll
    for (int i = 0; i < 23; ++i) {
        int d = lane + 32 * i;
        if (d < DIMV) {
            float y = v[i] * inv;
            __nv_bfloat16 h = __float2bfloat16(y);
            shh[d] = h;
            shl[d] = __float2bfloat16(y - __bfloat162float(h));
        }
    }
    // zero pad [720,768)
    {
        int d1 = 720 + lane;
        if (d1 < KP) { shh[d1] = __float2bfloat16(0.f); shl[d1] = __float2bfloat16(0.f); }
        int d2 = 752 + lane;
        if (d2 < KP) { shh[d2] = __float2bfloat16(0.f); shl[d2] = __float2bfloat16(0.f); }
    }
    __syncwarp();
    const uint4* s0 = sh4[w][0];
    const uint4* s1 = sh4[w][1];
    #pragma unroll
    for (int chunk = 0; chunk < 3; ++chunk) {
        g_chi4[(size_t)row * 96 + chunk * 32 + lane] = s0[chunk * 32 + lane];
        g_clo4[(size_t)row * 96 + chunk * 32 + lane] = s1[chunk * 32 + lane];
    }
}

// ---------------- 3: HMMA GEMM (sim = c @ P^T, split bf16) + fused epilogue ----------------
// CTA: 128x192, 512 thr (16 warps, 4x4), warp tile 32x48, BK=32, double-buffered cp.async.
#define STG 51200      // stage bytes: Ah 10240 | Al 10240 | Bh 15360 | Bl 15360 (pitch 80B)
#define DYN_SMEM (2 * STG)

__global__ void __launch_bounds__(512, 1) gemm_epi(const float* __restrict__ mg,
                                                   const float* __restrict__ mb,
                                                   const float* __restrict__ pg,
                                                   const float* __restrict__ pb,
                                                   const int*   __restrict__ gt,
                                                   float* __restrict__ out) {
    extern __shared__ char dsm[];
    __shared__ float sPg[KM], sPb[KM], sMg[NCLS], sMb[NCLS], bk[NCLS];
    __shared__ float seg_s[128 * NCLS];
    __shared__ float e_s[128 * NPRO];

    uint32_t tb = smem_u32(dsm);
    int t = threadIdx.x, lane = t & 31, w = t >> 5;
    int m0 = (w & 3) * 32, n0 = (w >> 2) * 48;
    int bm0 = blockIdx.x * 128;

    if (t < KM) { sPg[t] = pg[t]; sPb[t] = pb[t]; }
    if (t < NCLS) { sMg[t] = mg[t]; sMb[t] = mb[t]; bk[t] = 0.f; }

    float acc[2][6][4];
    #pragma unroll
    for (int a = 0; a < 2; ++a)
        #pragma unroll
        for (int b = 0; b < 6; ++b)
            #pragma unroll
            for (int c = 0; c < 4; ++c) acc[a][b][c] = 0.f;

    uint32_t aRow = (uint32_t)(m0 + (lane & 15)) * 80 + ((lane >> 4) << 4);
    uint32_t bRow = (uint32_t)(n0 + (lane & 15)) * 80 + ((lane >> 4) << 4);

    auto load_stage = [&](int c, int buf) {
        uint32_t st = tb + buf * STG;
        #pragma unroll
        for (int i = 0; i < 2; ++i) {
            int u = t + i * 512;
            int split = u >> 9, rem = u & 511;
            int row = rem >> 2, q = rem & 3;
            const uint4* src = (split ? g_clo4 : g_chi4) + (size_t)(bm0 + row) * 96 + c * 4 + q;
            CP16(st + split * 10240 + row * 80 + q * 16, src);
        }
        #pragma unroll
        for (int i = 0; i < 3; ++i) {
            int u = t + i * 512;
            int split = (u >= 768); int rem = u - split * 768;
            int row = rem >> 2, q = rem & 3;
            const uint4* src = (split ? g_Plo4 : g_Phi4) + (size_t)row * 96 + c * 4 + q;
            CP16(st + 20480 + split * 15360 + row * 80 + q * 16, src);
        }
        asm volatile("cp.async.commit_group;" ::: "memory");
    };

    auto compute = [&](int buf) {
        uint32_t stA = tb + buf * STG;
        uint32_t stB = stA + 20480;
        #pragma unroll
        for (int ks = 0; ks < 2; ++ks) {
            uint32_t kb = ks * 32;
            uint32_t ah[2][4], al[2][4];
            LDSM4(ah[0], stA + aRow + kb);
            LDSM4(ah[1], stA + aRow + 1280 + kb);
            LDSM4(al[0], stA + 10240 + aRow + kb);
            LDSM4(al[1], stA + 10240 + aRow + 1280 + kb);
            #pragma unroll
            for (int p = 0; p < 3; ++p) {
                uint32_t bh[4], bl[4];
                LDSM4(bh, stB + bRow + p * 1280 + kb);
                LDSM4(bl, stB + 15360 + bRow + p * 1280 + kb);
                #pragma unroll
                for (int mt = 0; mt < 2; ++mt) {
                    MMA_BF16(acc[mt][2 * p],     ah[mt], bh[0], bh[2]);
                    MMA_BF16(acc[mt][2 * p + 1], ah[mt], bh[1], bh[3]);
                    MMA_BF16(acc[mt][2 * p],     ah[mt], bl[0], bl[2]);
                    MMA_BF16(acc[mt][2 * p + 1], ah[mt], bl[1], bl[3]);
                    MMA_BF16(acc[mt][2 * p],     al[mt], bh[0], bh[2]);
                    MMA_BF16(acc[mt][2 * p + 1], al[mt], bh[1], bh[3]);
                }
            }
        }
    };

    load_stage(0, 0);
    for (int c = 0; c < 24; ++c) {
        if (c < 23) {
            load_stage(c + 1, (c + 1) & 1);
            asm volatile("cp.async.wait_group 1;" ::: "memory");
        } else {
            asm volatile("cp.async.wait_group 0;" ::: "memory");
        }
        __syncthreads();
        compute(c & 1);
        __syncthreads();
    }

    // ---------------- epilogue ----------------
    float* sim = (float*)dsm;     // [128][195] (pitch 195 floats, conflict-free)
    {
        int r0 = lane >> 2, cc = (lane & 3) * 2;
        #pragma unroll
        for (int mt = 0; mt < 2; ++mt) {
            #pragma unroll
            for (int j = 0; j < 6; ++j) {
                int row = m0 + mt * 16 + r0;
                int col = n0 + j * 8 + cc;
                sim[row * 195 + col]           = acc[mt][j][0];
                sim[row * 195 + col + 1]       = acc[mt][j][1];
                sim[(row + 8) * 195 + col]     = acc[mt][j][2];
                sim[(row + 8) * 195 + col + 1] = acc[mt][j][3];
            }
        }
    }
    __syncthreads();

    if (t < 128) {
        int n = bm0 + t;
        int gtn = gt[n];
        float s = 0.f, sq = 0.f, s19 = 0.f, sq19 = 0.f;
        float ev[NPRO];
        #pragma unroll
        for (int m = 0; m < NPRO; ++m) ev[m] = 0.f;
        for (int k = 0; k < NCLS; ++k) {
            float mx = -1e30f;
            #pragma unroll
            for (int m = 0; m < NPRO; ++m) {
                float v = sim[t * 195 + k * NPRO + m];
                s += v; sq += v * v;
                mx = fmaxf(mx, v);
                if (k == gtn) ev[m] = v;
            }
            seg_s[t * NCLS + k] = mx;
            s19 += mx; sq19 += mx * mx;
        }
        // out_seg LN + argmax
        float mu19 = s19 / (float)NCLS;
        float var19 = fmaxf(sq19 / (float)NCLS - mu19 * mu19, 0.f);
        float rv19 = rsqrtf(var19 + 1e-5f);
        float best = -1e30f; int bi = 0;
        for (int k = 0; k < NCLS; ++k) {
            float o = (seg_s[t * NCLS + k] - mu19) * rv19 * sMg[k] + sMb[k];
            seg_s[t * NCLS + k] = o;
            if (o > best) { best = o; bi = k; }
        }
        g_corr[n] = (bi == gtn) ? 1 : 0;
        atomicAdd(&bk[gtn], 1.f);
        #pragma unroll
        for (int m = 0; m < NPRO; ++m) e_s[t * NPRO + m] = expf(ev[m] * SKEPS_INV);
        // contrast LN (in place)
        float mu = s / (float)KM;
        float var = fmaxf(sq / (float)KM - mu * mu, 0.f);
        float rv = rsqrtf(var + 1e-5f);
        for (int j = 0; j < KM; ++j)
            sim[t * 195 + j] = (sim[t * 195 + j] - mu) * rv * sPg[j] + sPb[j];
    }
    __syncthreads();

    // coalesced copy-out
    for (int idx = t; idx < 128 * KM; idx += 512) {
        int row = idx / KM, j = idx - row * KM;
        out[OFF_CON + (size_t)bm0 * KM + idx] = sim[row * 195 + j];
    }
    for (int idx = t; idx < 128 * NCLS; idx += 512)
        out[OFF_SEG + (size_t)bm0 * NCLS + idx] = seg_s[idx];
    for (int idx = t; idx < 128 * NPRO; idx += 512)
        g_E[(size_t)bm0 * NPRO + idx] = e_s[idx];
    if (t < NCLS) atomicAdd(&g_Bk[t], bk[t]);
}

// ---------------- 4: Sinkhorn column-sum accumulation ----------------
__global__ void sk_accum(const int* __restrict__ gt, int pass) {
    __shared__ float Sl[KM];
    int t = threadIdx.x;
    if (t < KM) Sl[t] = 0.f;
    __syncthreads();
    int n = blockIdx.x * blockDim.x + t;
    if (n < NPIX) {
        int k = gt[n];
        const float* E = g_E + (size_t)n * NPRO;
        float e[NPRO];
        #pragma unroll
        for (int m = 0; m < NPRO; ++m) e[m] = E[m];
        float a = 1.f;
        if (pass) {
            const float* bb = g_b + k * NPRO;
            float d = 0.f;
            #pragma unroll
            for (int m = 0; m < NPRO; ++m) d += e[m] * bb[m];
            a = 1.f / (g_Bk[k] * d);
        }
        #pragma unroll
        for (int m = 0; m < NPRO; ++m) atomicAdd(&Sl[k * NPRO + m], e[m] * a);
    }
    __syncthreads();
    if (t < KM) atomicAdd(&g_S[t], Sl[t]);
}

__global__ void sk_fin() {
    int t = threadIdx.x;
    if (t < KM) {
        float s = g_S[t];
        g_b[t] = (s > 0.f) ? 1.f / (10.f * s) : 0.f;
        g_S[t] = 0.f;
    }
}

// ---------------- 5: hard assignment + proto_target ----------------
__global__ void sk_final(const int* __restrict__ gt, float* __restrict__ out) {
    int n = blockIdx.x * blockDim.x + threadIdx.x;
    if (n >= NPIX) return;
    int k = gt[n];
    const float* E = g_E + (size_t)n * NPRO;
    const float* bb = g_b + k * NPRO;
    float best = -1.f; int bi = 0;
    #pragma unroll
    for (int m = 0; m < NPRO; ++m) {
        float wv = E[m] * bb[m];
        if (wv > best) { best = wv; bi = m; }
    }
    out[OFF_PT + n] = (float)(bi + NPRO * k);
    g_idx[n] = (unsigned char)bi;
    if (g_corr[n]) atomicAdd(&g_nkm[k * NPRO + bi], 1.f);
}

// ---------------- 6: accumulate f over correct pixels ----------------
__global__ void f_accum(const int* __restrict__ gt) {
    int warp = (blockIdx.x * blockDim.x + threadIdx.x) >> 5;
    int lane = threadIdx.x & 31;
    if (warp >= NPIX) return;
    if (!g_corr[warp]) return;
    int k = gt[warp], m = g_idx[warp];
    float* f = g_f + (size_t)(k * NPRO + m) * DIMV;
    const __nv_bfloat16* hi = (const __nv_bfloat16*)g_chi4 + (size_t)warp * KP;
    const __nv_bfloat16* lo = (const __nv_bfloat16*)g_clo4 + (size_t)warp * KP;
    for (int d = lane; d < DIMV; d += 32)
        atomicAdd(&f[d], __bfloat162float(hi[d]) + __bfloat162float(lo[d]));
}

// ---------------- 7: prototype EMA update ----------------
__global__ void update_protos(float* __restrict__ out) {
    int row = blockIdx.x;                 // 0..189
    int k = row / NPRO;
    const float* f = g_f + (size_t)row * DIMV;
    const float* p = g_Pn + (size_t)row * DIMV;

    float sq = 0.f;
    for (int d = threadIdx.x; d < DIMV; d += blockDim.x) { float v = f[d]; sq += v * v; }
    sq = block_sum_256(sq);
    float invf = 1.f / fmaxf(sqrtf(sq), 1e-12f);

    float nk = g_nkm[row];
    float ksum = 0.f;
    #pragma unroll
    for (int m = 0; m < NPRO; ++m) ksum += g_nkm[k * NPRO + m];
    bool valid = (nk != 0.f) && (ksum > 0.f);

    float squ = 0.f;
    for (int d = threadIdx.x; d < DIMV; d += blockDim.x) {
        float pv = p[d];
        float u = valid ? (0.999f * pv + 0.001f * f[d] * invf) : pv;
        squ += u * u;
    }
    squ = block_sum_256(squ);
    float invu = 1.f / fmaxf(sqrtf(squ), 1e-12f);
    for (int d = threadIdx.x; d < DIMV; d += blockDim.x) {
        float pv = p[d];
        float u = valid ? (0.999f * pv + 0.001f * f[d] * invf) : pv;
        out[OFF_PN + (size_t)row * DIMV + d] = u * invu;
    }
}

// ---------------- launch ----------------
extern "C" void kernel_launch(void* const* d_in, const int* in_sizes, int n_in,
                              void* d_out, int out_size) {
    const float* x     = (const float*)d_in[0];
    const float* proto = (const float*)d_in[1];
    const float* fn_g  = (const float*)d_in[2];
    const float* fn_b  = (const float*)d_in[3];
    const float* mn_g  = (const float*)d_in[4];
    const float* mn_b  = (const float*)d_in[5];
    const float* pn_g  = (const float*)d_in[6];
    const float* pn_b  = (const float*)d_in[7];
    const int*   gt    = (const int*)d_in[8];
    float* out = (float*)d_out;

    cudaFuncSetAttribute(gemm_epi, cudaFuncAttributeMaxDynamicSharedMemorySize, DYN_SMEM);

    zero_kernel<<<540, 256>>>();
    norm_protos<<<192, 256>>>(proto);
    prep_pixels<<<NPIX / 8, 256>>>(x, fn_g, fn_b);
    gemm_epi<<<NPIX / 128, 512, DYN_SMEM>>>(mn_g, mn_b, pn_g, pn_b, gt, out);
    sk_accum<<<NPIX / 256, 256>>>(gt, 0);
    sk_fin<<<1, 192>>>();
    sk_accum<<<NPIX / 256, 256>>>(gt, 1);
    sk_fin<<<1, 192>>>();
    sk_accum<<<NPIX / 256, 256>>>(gt, 1);
    sk_fin<<<1, 192>>>();
    sk_final<<<NPIX / 256, 256>>>(gt, out);
    f_accum<<<NPIX / 8, 256>>>(gt);
    update_protos<<<KM, 256>>>(out);
}

// round 4
// speedup vs baseline: 2.3927x; 1.0208x over previous
#include <cuda_runtime.h>
#include <cuda_bf16.h>
#include <math.h>
#include <stdint.h>

// ---------------- problem constants ----------------
#define NPIX 131072
#define DIMV 720
#define KP   768          // K padded (24 chunks of 32)
#define NCLS 19
#define NPRO 10
#define KM   190
#define SKEPS_INV 20.0f

// output layout (fp32): out_seg[N,19] | contrast[N,190] | proto_target[N] | protos_new[190,720]
#define OFF_SEG 0
#define OFF_CON ((size_t)NPIX * 19)
#define OFF_PT  (OFF_CON + (size_t)NPIX * 190)
#define OFF_PN  (OFF_PT + (size_t)NPIX)

// ---------------- device scratch ----------------
__device__ uint4 g_chi4[(size_t)NPIX * 96];   // pixel embeddings hi bf16 [N][768]
__device__ uint4 g_clo4[(size_t)NPIX * 96];   // pixel embeddings lo bf16
__device__ uint4 g_Phi4[192 * 96];            // protos hi bf16 [192][768] (rows 190,191 zero)
__device__ uint4 g_Plo4[192 * 96];            // protos lo bf16
__device__ float g_Pn[KM * DIMV];             // normalized protos fp32
__device__ float g_E[(size_t)NPIX * NPRO];    // exp(sim_gt/eps)
__device__ float g_S[KM];
__device__ float g_b[KM];
__device__ float g_Bk[NCLS];
__device__ float g_nkm[KM];
__device__ float g_f[KM * DIMV];
__device__ unsigned char g_corr[NPIX];
__device__ unsigned char g_idx[NPIX];

// ---------------- generic helpers ----------------
__device__ __forceinline__ float warp_sum(float v) {
    #pragma unroll
    for (int o = 16; o; o >>= 1) v += __shfl_xor_sync(0xffffffffu, v, o);
    return v;
}

__device__ __forceinline__ float block_sum_256(float v) {
    __shared__ float sh[8];
    int lane = threadIdx.x & 31, w = threadIdx.x >> 5;
    v = warp_sum(v);
    if (lane == 0) sh[w] = v;
    __syncthreads();
    float r = 0.f;
    if (threadIdx.x < 8) r = sh[threadIdx.x];
    if (w == 0) {
        #pragma unroll
        for (int o = 4; o; o >>= 1) r += __shfl_xor_sync(0xffffffffu, r, o);
    }
    if (threadIdx.x == 0) sh[0] = r;
    __syncthreads();
    r = sh[0];
    __syncthreads();
    return r;
}

__device__ __forceinline__ uint32_t smem_u32(const void* p) {
    uint32_t a;
    asm("{ .reg .u64 t; cvta.to.shared.u64 t, %1; cvt.u32.u64 %0, t; }" : "=r"(a) : "l"(p));
    return a;
}

// ---------------- PTX macros (family-common, compile on compute_103) ----------------
#define LDSM4(r, addr) \
    asm volatile("ldmatrix.sync.aligned.m8n8.x4.shared.b16 {%0,%1,%2,%3}, [%4];" \
        : "=r"((r)[0]), "=r"((r)[1]), "=r"((r)[2]), "=r"((r)[3]) : "r"(addr))

#define MMA_BF16(c, a, b0, b1) \
    asm volatile("mma.sync.aligned.m16n8k16.row.col.f32.bf16.bf16.f32 " \
        "{%0,%1,%2,%3}, {%4,%5,%6,%7}, {%8,%9}, {%0,%1,%2,%3};" \
        : "+f"((c)[0]), "+f"((c)[1]), "+f"((c)[2]), "+f"((c)[3]) \
        : "r"((a)[0]), "r"((a)[1]), "r"((a)[2]), "r"((a)[3]), "r"(b0), "r"(b1))

#define CP16(dst, src) \
    asm volatile("cp.async.cg.shared.global [%0], [%1], 16;" :: "r"(dst), "l"(src) : "memory")

// ---------------- 0: zero accumulators ----------------
__global__ void zero_kernel() {
    int i = blockIdx.x * blockDim.x + threadIdx.x;
    int stride = gridDim.x * blockDim.x;
    for (int j = i; j < KM * DIMV; j += stride) g_f[j] = 0.f;
    for (int j = i; j < KM; j += stride) { g_S[j] = 0.f; g_nkm[j] = 0.f; }
    for (int j = i; j < NCLS; j += stride) g_Bk[j] = 0.f;
}

// ---------------- 1: l2-normalize prototypes -> bf16 hi/lo + fp32 ----------------
__global__ void norm_protos(const float* __restrict__ proto) {
    int row = blockIdx.x;                   // 0..191 (190,191 zero pad)
    __nv_bfloat16* hi = (__nv_bfloat16*)g_Phi4 + (size_t)row * KP;
    __nv_bfloat16* lo = (__nv_bfloat16*)g_Plo4 + (size_t)row * KP;
    float inv = 0.f;
    const float* p = proto + (size_t)row * DIMV;
    if (row < KM) {
        float sq = 0.f;
        for (int d = threadIdx.x; d < DIMV; d += blockDim.x) { float v = p[d]; sq += v * v; }
        sq = block_sum_256(sq);
        inv = 1.f / fmaxf(sqrtf(sq), 1e-12f);
    } else {
        block_sum_256(0.f);
    }
    for (int d = threadIdx.x; d < KP; d += blockDim.x) {
        float v = (row < KM && d < DIMV) ? p[d] * inv : 0.f;
        __nv_bfloat16 h = __float2bfloat16(v);
        hi[d] = h;
        lo[d] = __float2bfloat16(v - __bfloat162float(h));
        if (row < KM && d < DIMV) g_Pn[(size_t)row * DIMV + d] = v;
    }
}

// ---------------- 2: per-pixel LN + L2 -> bf16 hi/lo (coalesced via SMEM staging) ----------------
__global__ void prep_pixels(const float* __restrict__ x,
                            const float* __restrict__ fg,
                            const float* __restrict__ fb) {
    __shared__ uint4 sh4[8][2][96];          // [warp][hi/lo][96 uint4]
    int w = threadIdx.x >> 5, lane = threadIdx.x & 31;
    int row = blockIdx.x * 8 + w;
    const float* xr = x + (size_t)row * DIMV;
    __nv_bfloat16* shh = (__nv_bfloat16*)sh4[w][0];
    __nv_bfloat16* shl = (__nv_bfloat16*)sh4[w][1];

    float v[23];
    float s = 0.f;
    #pragma unroll
    for (int i = 0; i < 23; ++i) {
        int d = lane + 32 * i;
        float t = (d < DIMV) ? xr[d] : 0.f;
        v[i] = t; s += t;
    }
    s = warp_sum(s);
    float mu = s / (float)DIMV;
    float sq = 0.f;
    #pragma unroll
    for (int i = 0; i < 23; ++i) {
        int d = lane + 32 * i;
        if (d < DIMV) { float t = v[i] - mu; sq += t * t; }
    }
    sq = warp_sum(sq);
    float r = rsqrtf(sq / (float)DIMV + 1e-5f);
    float ny = 0.f;
    #pragma unroll
    for (int i = 0; i < 23; ++i) {
        int d = lane + 32 * i;
        if (d < DIMV) {
            float y = (v[i] - mu) * r * fg[d] + fb[d];
            v[i] = y; ny += y * y;
        }
    }
    ny = warp_sum(ny);
    float inv = 1.f / fmaxf(sqrtf(ny), 1e-12f);
    #pragma unroll
    for (int i = 0; i < 23; ++i) {
        int d = lane + 32 * i;
        if (d < DIMV) {
            float y = v[i] * inv;
            __nv_bfloat16 h = __float2bfloat16(y);
            shh[d] = h;
            shl[d] = __float2bfloat16(y - __bfloat162float(h));
        }
    }
    // zero pad [720,768)
    {
        int d1 = 720 + lane;
        if (d1 < KP) { shh[d1] = __float2bfloat16(0.f); shl[d1] = __float2bfloat16(0.f); }
        int d2 = 752 + lane;
        if (d2 < KP) { shh[d2] = __float2bfloat16(0.f); shl[d2] = __float2bfloat16(0.f); }
    }
    __syncwarp();
    const uint4* s0 = sh4[w][0];
    const uint4* s1 = sh4[w][1];
    #pragma unroll
    for (int chunk = 0; chunk < 3; ++chunk) {
        g_chi4[(size_t)row * 96 + chunk * 32 + lane] = s0[chunk * 32 + lane];
        g_clo4[(size_t)row * 96 + chunk * 32 + lane] = s1[chunk * 32 + lane];
    }
}

// ---------------- 3: HMMA GEMM (sim = c @ P^T, split bf16) + fused epilogue ----------------
// CTA: 128x192, 512 thr (16 warps, 4x4), warp tile 32x48, BK=32, 3-stage cp.async pipeline.
#define STG 51200      // stage bytes: Ah 10240 | Al 10240 | Bh 15360 | Bl 15360 (pitch 80B)
#define NSTG 3
#define DYN_SMEM (NSTG * STG)

__global__ void __launch_bounds__(512, 1) gemm_epi(const float* __restrict__ mg,
                                                   const float* __restrict__ mb,
                                                   const float* __restrict__ pg,
                                                   const float* __restrict__ pb,
                                                   const int*   __restrict__ gt,
                                                   float* __restrict__ out) {
    extern __shared__ char dsm[];
    __shared__ float sPg[KM], sPb[KM], sMg[NCLS], sMb[NCLS], bk[NCLS];
    __shared__ float seg_s[128 * NCLS];
    __shared__ float e_s[128 * NPRO];

    uint32_t tb = smem_u32(dsm);
    int t = threadIdx.x, lane = t & 31, w = t >> 5;
    int m0 = (w & 3) * 32, n0 = (w >> 2) * 48;
    int bm0 = blockIdx.x * 128;

    if (t < KM) { sPg[t] = pg[t]; sPb[t] = pb[t]; }
    if (t < NCLS) { sMg[t] = mg[t]; sMb[t] = mb[t]; bk[t] = 0.f; }

    float acc[2][6][4];
    #pragma unroll
    for (int a = 0; a < 2; ++a)
        #pragma unroll
        for (int b = 0; b < 6; ++b)
            #pragma unroll
            for (int c = 0; c < 4; ++c) acc[a][b][c] = 0.f;

    uint32_t aRow = (uint32_t)(m0 + (lane & 15)) * 80 + ((lane >> 4) << 4);
    uint32_t bRow = (uint32_t)(n0 + (lane & 15)) * 80 + ((lane >> 4) << 4);

    auto load_stage = [&](int c, int buf) {
        uint32_t st = tb + buf * STG;
        #pragma unroll
        for (int i = 0; i < 2; ++i) {
            int u = t + i * 512;
            int split = u >> 9, rem = u & 511;
            int row = rem >> 2, q = rem & 3;
            const uint4* src = (split ? g_clo4 : g_chi4) + (size_t)(bm0 + row) * 96 + c * 4 + q;
            CP16(st + split * 10240 + row * 80 + q * 16, src);
        }
        #pragma unroll
        for (int i = 0; i < 3; ++i) {
            int u = t + i * 512;
            int split = (u >= 768); int rem = u - split * 768;
            int row = rem >> 2, q = rem & 3;
            const uint4* src = (split ? g_Plo4 : g_Phi4) + (size_t)row * 96 + c * 4 + q;
            CP16(st + 20480 + split * 15360 + row * 80 + q * 16, src);
        }
        asm volatile("cp.async.commit_group;" ::: "memory");
    };

    auto compute = [&](int buf) {
        uint32_t stA = tb + buf * STG;
        uint32_t stB = stA + 20480;
        #pragma unroll
        for (int ks = 0; ks < 2; ++ks) {
            uint32_t kb = ks * 32;
            uint32_t ah[2][4], al[2][4];
            LDSM4(ah[0], stA + aRow + kb);
            LDSM4(ah[1], stA + aRow + 1280 + kb);
            LDSM4(al[0], stA + 10240 + aRow + kb);
            LDSM4(al[1], stA + 10240 + aRow + 1280 + kb);
            #pragma unroll
            for (int p = 0; p < 3; ++p) {
                uint32_t bh[4], bl[4];
                LDSM4(bh, stB + bRow + p * 1280 + kb);
                LDSM4(bl, stB + 15360 + bRow + p * 1280 + kb);
                #pragma unroll
                for (int mt = 0; mt < 2; ++mt) {
                    MMA_BF16(acc[mt][2 * p],     ah[mt], bh[0], bh[2]);
                    MMA_BF16(acc[mt][2 * p + 1], ah[mt], bh[1], bh[3]);
                    MMA_BF16(acc[mt][2 * p],     ah[mt], bl[0], bl[2]);
                    MMA_BF16(acc[mt][2 * p + 1], ah[mt], bl[1], bl[3]);
                    MMA_BF16(acc[mt][2 * p],     al[mt], bh[0], bh[2]);
                    MMA_BF16(acc[mt][2 * p + 1], al[mt], bh[1], bh[3]);
                }
            }
        }
    };

    // ---------------- 3-stage pipelined mainloop, one barrier per chunk ----------------
    load_stage(0, 0);
    load_stage(1, 1);
    #pragma unroll 1
    for (int c = 0; c < 24; ++c) {
        if (c < 23) asm volatile("cp.async.wait_group 1;" ::: "memory");
        else        asm volatile("cp.async.wait_group 0;" ::: "memory");
        __syncthreads();
        if (c + 2 < 24) load_stage(c + 2, (c + 2) % NSTG);
        compute(c % NSTG);
    }
    __syncthreads();

    // ---------------- epilogue ----------------
    float* sim = (float*)dsm;     // [128][195] (pitch 195 floats, conflict-free)
    {
        int r0 = lane >> 2, cc = (lane & 3) * 2;
        #pragma unroll
        for (int mt = 0; mt < 2; ++mt) {
            #pragma unroll
            for (int j = 0; j < 6; ++j) {
                int row = m0 + mt * 16 + r0;
                int col = n0 + j * 8 + cc;
                sim[row * 195 + col]           = acc[mt][j][0];
                sim[row * 195 + col + 1]       = acc[mt][j][1];
                sim[(row + 8) * 195 + col]     = acc[mt][j][2];
                sim[(row + 8) * 195 + col + 1] = acc[mt][j][3];
            }
        }
    }
    __syncthreads();

    if (t < 128) {
        int n = bm0 + t;
        int gtn = gt[n];
        float s = 0.f, sq = 0.f, s19 = 0.f, sq19 = 0.f;
        float ev[NPRO];
        #pragma unroll
        for (int m = 0; m < NPRO; ++m) ev[m] = 0.f;
        for (int k = 0; k < NCLS; ++k) {
            float mx = -1e30f;
            #pragma unroll
            for (int m = 0; m < NPRO; ++m) {
                float v = sim[t * 195 + k * NPRO + m];
                s += v; sq += v * v;
                mx = fmaxf(mx, v);
                if (k == gtn) ev[m] = v;
            }
            seg_s[t * NCLS + k] = mx;
            s19 += mx; sq19 += mx * mx;
        }
        // out_seg LN + argmax
        float mu19 = s19 / (float)NCLS;
        float var19 = fmaxf(sq19 / (float)NCLS - mu19 * mu19, 0.f);
        float rv19 = rsqrtf(var19 + 1e-5f);
        float best = -1e30f; int bi = 0;
        for (int k = 0; k < NCLS; ++k) {
            float o = (seg_s[t * NCLS + k] - mu19) * rv19 * sMg[k] + sMb[k];
            seg_s[t * NCLS + k] = o;
            if (o > best) { best = o; bi = k; }
        }
        g_corr[n] = (bi == gtn) ? 1 : 0;
        atomicAdd(&bk[gtn], 1.f);
        #pragma unroll
        for (int m = 0; m < NPRO; ++m) e_s[t * NPRO + m] = expf(ev[m] * SKEPS_INV);
        // contrast LN (in place)
        float mu = s / (float)KM;
        float var = fmaxf(sq / (float)KM - mu * mu, 0.f);
        float rv = rsqrtf(var + 1e-5f);
        for (int j = 0; j < KM; ++j)
            sim[t * 195 + j] = (sim[t * 195 + j] - mu) * rv * sPg[j] + sPb[j];
    }
    __syncthreads();

    // coalesced copy-out
    for (int idx = t; idx < 128 * KM; idx += 512) {
        int row = idx / KM, j = idx - row * KM;
        out[OFF_CON + (size_t)bm0 * KM + idx] = sim[row * 195 + j];
    }
    for (int idx = t; idx < 128 * NCLS; idx += 512)
        out[OFF_SEG + (size_t)bm0 * NCLS + idx] = seg_s[idx];
    for (int idx = t; idx < 128 * NPRO; idx += 512)
        g_E[(size_t)bm0 * NPRO + idx] = e_s[idx];
    if (t < NCLS) atomicAdd(&g_Bk[t], bk[t]);
}

// ---------------- 4: Sinkhorn column-sum accumulation ----------------
__global__ void sk_accum(const int* __restrict__ gt, int pass) {
    __shared__ float Sl[KM];
    int t = threadIdx.x;
    if (t < KM) Sl[t] = 0.f;
    __syncthreads();
    int n = blockIdx.x * blockDim.x + t;
    if (n < NPIX) {
        int k = gt[n];
        const float* E = g_E + (size_t)n * NPRO;
        float e[NPRO];
        #pragma unroll
        for (int m = 0; m < NPRO; ++m) e[m] = E[m];
        float a = 1.f;
        if (pass) {
            const float* bb = g_b + k * NPRO;
            float d = 0.f;
            #pragma unroll
            for (int m = 0; m < NPRO; ++m) d += e[m] * bb[m];
            a = 1.f / (g_Bk[k] * d);
        }
        #pragma unroll
        for (int m = 0; m < NPRO; ++m) atomicAdd(&Sl[k * NPRO + m], e[m] * a);
    }
    __syncthreads();
    if (t < KM) atomicAdd(&g_S[t], Sl[t]);
}

__global__ void sk_fin() {
    int t = threadIdx.x;
    if (t < KM) {
        float s = g_S[t];
        g_b[t] = (s > 0.f) ? 1.f / (10.f * s) : 0.f;
        g_S[t] = 0.f;
    }
}

// ---------------- 5: hard assignment + proto_target ----------------
__global__ void sk_final(const int* __restrict__ gt, float* __restrict__ out) {
    int n = blockIdx.x * blockDim.x + threadIdx.x;
    if (n >= NPIX) return;
    int k = gt[n];
    const float* E = g_E + (size_t)n * NPRO;
    const float* bb = g_b + k * NPRO;
    float best = -1.f; int bi = 0;
    #pragma unroll
    for (int m = 0; m < NPRO; ++m) {
        float wv = E[m] * bb[m];
        if (wv > best) { best = wv; bi = m; }
    }
    out[OFF_PT + n] = (float)(bi + NPRO * k);
    g_idx[n] = (unsigned char)bi;
    if (g_corr[n]) atomicAdd(&g_nkm[k * NPRO + bi], 1.f);
}

// ---------------- 6: accumulate f over correct pixels ----------------
__global__ void f_accum(const int* __restrict__ gt) {
    int warp = (blockIdx.x * blockDim.x + threadIdx.x) >> 5;
    int lane = threadIdx.x & 31;
    if (warp >= NPIX) return;
    if (!g_corr[warp]) return;
    int k = gt[warp], m = g_idx[warp];
    float* f = g_f + (size_t)(k * NPRO + m) * DIMV;
    const __nv_bfloat16* hi = (const __nv_bfloat16*)g_chi4 + (size_t)warp * KP;
    const __nv_bfloat16* lo = (const __nv_bfloat16*)g_clo4 + (size_t)warp * KP;
    for (int d = lane; d < DIMV; d += 32)
        atomicAdd(&f[d], __bfloat162float(hi[d]) + __bfloat162float(lo[d]));
}

// ---------------- 7: prototype EMA update ----------------
__global__ void update_protos(float* __restrict__ out) {
    int row = blockIdx.x;                 // 0..189
    int k = row / NPRO;
    const float* f = g_f + (size_t)row * DIMV;
    const float* p = g_Pn + (size_t)row * DIMV;

    float sq = 0.f;
    for (int d = threadIdx.x; d < DIMV; d += blockDim.x) { float v = f[d]; sq += v * v; }
    sq = block_sum_256(sq);
    float invf = 1.f / fmaxf(sqrtf(sq), 1e-12f);

    float nk = g_nkm[row];
    float ksum = 0.f;
    #pragma unroll
    for (int m = 0; m < NPRO; ++m) ksum += g_nkm[k * NPRO + m];
    bool valid = (nk != 0.f) && (ksum > 0.f);

    float squ = 0.f;
    for (int d = threadIdx.x; d < DIMV; d += blockDim.x) {
        float pv = p[d];
        float u = valid ? (0.999f * pv + 0.001f * f[d] * invf) : pv;
        squ += u * u;
    }
    squ = block_sum_256(squ);
    float invu = 1.f / fmaxf(sqrtf(squ), 1e-12f);
    for (int d = threadIdx.x; d < DIMV; d += blockDim.x) {
        float pv = p[d];
        float u = valid ? (0.999f * pv + 0.001f * f[d] * invf) : pv;
        out[OFF_PN + (size_t)row * DIMV + d] = u * invu;
    }
}

// ---------------- launch ----------------
extern "C" void kernel_launch(void* const* d_in, const int* in_sizes, int n_in,
                              void* d_out, int out_size) {
    const float* x     = (const float*)d_in[0];
    const float* proto = (const float*)d_in[1];
    const float* fn_g  = (const float*)d_in[2];
    const float* fn_b  = (const float*)d_in[3];
    const float* mn_g  = (const float*)d_in[4];
    const float* mn_b  = (const float*)d_in[5];
    const float* pn_g  = (const float*)d_in[6];
    const float* pn_b  = (const float*)d_in[7];
    const int*   gt    = (const int*)d_in[8];
    float* out = (float*)d_out;

    cudaFuncSetAttribute(gemm_epi, cudaFuncAttributeMaxDynamicSharedMemorySize, DYN_SMEM);

    zero_kernel<<<540, 256>>>();
    norm_protos<<<192, 256>>>(proto);
    prep_pixels<<<NPIX / 8, 256>>>(x, fn_g, fn_b);
    gemm_epi<<<NPIX / 128, 512, DYN_SMEM>>>(mn_g, mn_b, pn_g, pn_b, gt, out);
    sk_accum<<<NPIX / 256, 256>>>(gt, 0);
    sk_fin<<<1, 192>>>();
    sk_accum<<<NPIX / 256, 256>>>(gt, 1);
    sk_fin<<<1, 192>>>();
    sk_accum<<<NPIX / 256, 256>>>(gt, 1);
    sk_fin<<<1, 192>>>();
    sk_final<<<NPIX / 256, 256>>>(gt, out);
    f_accum<<<NPIX / 8, 256>>>(gt);
    update_protos<<<KM, 256>>>(out);
}